// round 11
// baseline (speedup 1.0000x reference)
#include <cuda_runtime.h>
#include <cuda_fp16.h>

#define M_TOTAL 4096
#define N_TOTAL 11008
#define K_TOTAL 4096

// Scratch: fp16 copies of x and unpacked integer weights (exact in fp16).
__device__ __align__(16) __half g_x[(size_t)M_TOTAL * K_TOTAL];   // 33.5 MB
__device__ __align__(16) __half g_w[(size_t)N_TOTAL * K_TOTAL];   // 90.2 MB

#define BM 128
#define BN 256
#define BK 32
#define STAGES 6
#define KT (K_TOTAL / BK)          // 128
#define AST 40
#define ASTAGE (BM * AST)
#define BSTAGE (BN * AST)

#define TOTAL_TILES ((M_TOTAL / BM) * (N_TOTAL / BN))   // 1376
#define MAIN_TILES  1332                                 // 9 * 148
#define TAIL_TILES  (TOTAL_TILES - MAIN_TILES)           // 44
#define KSPLITS     3
#define PART_CTAS   (TAIL_TILES * KSPLITS)               // 132

// fp32 partials for the K-split tail: [split][tile][128][256]
__device__ __align__(16) float g_part[(size_t)KSPLITS * TAIL_TILES * BM * BN]; // 17.3MB

// ---------------------------------------------------------------------------
// Pre-pass 1: x fp32 -> fp16
// ---------------------------------------------------------------------------
__global__ void convert_x_kernel(const float* __restrict__ x) {
    int i = blockIdx.x * blockDim.x + threadIdx.x;
    const float4* xv = (const float4*)x;
    float4 a = xv[2 * i];
    float4 b = xv[2 * i + 1];
    __half2 h0 = __floats2half2_rn(a.x, a.y);
    __half2 h1 = __floats2half2_rn(a.z, a.w);
    __half2 h2 = __floats2half2_rn(b.x, b.y);
    __half2 h3 = __floats2half2_rn(b.z, b.w);
    uint4 u;
    u.x = *(const unsigned int*)&h0;
    u.y = *(const unsigned int*)&h1;
    u.z = *(const unsigned int*)&h2;
    u.w = *(const unsigned int*)&h3;
    ((uint4*)g_x)[i] = u;
}

// ---------------------------------------------------------------------------
// Pre-pass 2: unpack int4 nibbles -> fp16 integers (exact; scale in epilogue)
// 16 int32 per thread (4x int4 loads) for deep MLP.
// ---------------------------------------------------------------------------
__device__ __forceinline__ __half2 unpack_pair(int v) {
    int lo = (v & 15) - 8;
    int hi = ((v >> 4) & 15) - 8;
    return __halves2half2(__int2half_rn(lo), __int2half_rn(hi));
}

__device__ __forceinline__ uint4 unpack4(int4 p) {
    uint4 u;
    __half2 h0 = unpack_pair(p.x), h1 = unpack_pair(p.y);
    __half2 h2 = unpack_pair(p.z), h3 = unpack_pair(p.w);
    u.x = *(const unsigned int*)&h0; u.y = *(const unsigned int*)&h1;
    u.z = *(const unsigned int*)&h2; u.w = *(const unsigned int*)&h3;
    return u;
}

__global__ void convert_w_kernel(const int* __restrict__ wp) {
    int i = blockIdx.x * blockDim.x + threadIdx.x;
    int4 p0 = ((const int4*)wp)[4 * i];
    int4 p1 = ((const int4*)wp)[4 * i + 1];
    int4 p2 = ((const int4*)wp)[4 * i + 2];
    int4 p3 = ((const int4*)wp)[4 * i + 3];
    ((uint4*)g_w)[4 * i]     = unpack4(p0);
    ((uint4*)g_w)[4 * i + 1] = unpack4(p1);
    ((uint4*)g_w)[4 * i + 2] = unpack4(p2);
    ((uint4*)g_w)[4 * i + 3] = unpack4(p3);
}

// ---------------------------------------------------------------------------
// GEMM machinery (round-8 code; STAGES 5 -> 6 only)
// ---------------------------------------------------------------------------
__device__ __forceinline__ void cp_async16(void* smem_p, const void* gmem) {
    unsigned int s = (unsigned int)__cvta_generic_to_shared(smem_p);
    asm volatile("cp.async.cg.shared.global [%0], [%1], 16;\n" :: "r"(s), "l"(gmem));
}

__device__ __forceinline__ void tile_coords(int pid, int& m0, int& n0) {
    const int PN = N_TOTAL / BN;   // 43
    const int GM = 16;
    int group = pid / (GM * PN);
    int rem   = pid % (GM * PN);
    m0 = (group * GM + (rem % GM)) * BM;
    n0 = (rem / GM) * BN;
}

__device__ __forceinline__ void frag_a_load(unsigned int a[4][4],
                                            const __half* A, int wm,
                                            int lane, int ks) {
    #pragma unroll
    for (int mt = 0; mt < 4; mt++) {
        int r  = wm + mt * 16 + (lane & 15);
        int kk = ks * 16 + ((lane >> 4) << 3);
        unsigned int addr = (unsigned int)__cvta_generic_to_shared(&A[r * AST + kk]);
        asm volatile("ldmatrix.sync.aligned.m8n8.x4.shared.b16 {%0,%1,%2,%3}, [%4];"
                     : "=r"(a[mt][0]), "=r"(a[mt][1]), "=r"(a[mt][2]), "=r"(a[mt][3])
                     : "r"(addr));
    }
}

__device__ __forceinline__ void frag_b_load8(unsigned int b[8][2],
                                             const __half* B, int wn,
                                             int lane, int ks) {
    #pragma unroll
    for (int np = 0; np < 4; np++) {
        int r  = wn + np * 16 + (((lane >> 4) & 1) << 3) + (lane & 7);
        int kk = ks * 16 + (((lane >> 3) & 1) << 3);
        unsigned int addr = (unsigned int)__cvta_generic_to_shared(&B[r * AST + kk]);
        asm volatile("ldmatrix.sync.aligned.m8n8.x4.shared.b16 {%0,%1,%2,%3}, [%4];"
                     : "=r"(b[2 * np][0]), "=r"(b[2 * np][1]),
                       "=r"(b[2 * np + 1][0]), "=r"(b[2 * np + 1][1])
                     : "r"(addr));
    }
}

#define MMA16816(acc, a, b)                                                  \
    asm volatile(                                                            \
        "mma.sync.aligned.m16n8k16.row.col.f32.f16.f16.f32 "                 \
        "{%0,%1,%2,%3}, {%4,%5,%6,%7}, {%8,%9}, {%0,%1,%2,%3};"              \
        : "+f"((acc)[0]), "+f"((acc)[1]), "+f"((acc)[2]), "+f"((acc)[3])     \
        : "r"((a)[0]), "r"((a)[1]), "r"((a)[2]), "r"((a)[3]),                \
          "r"((b)[0]), "r"((b)[1]))

__device__ __forceinline__ void gemm_body(__half* As, __half* Bs,
                                          int m0, int n0, int kbase, int ktiles,
                                          int tid, int lane, int wm, int wn,
                                          float acc[4][8][4]) {
    auto load_tiles = [&](int buf, int koff) {
        #pragma unroll
        for (int j = 0; j < 2; j++) {
            int c   = tid + j * 256;
            int row = c >> 2;
            int ko  = (c & 3) * 8;
            cp_async16(&As[buf * ASTAGE + row * AST + ko],
                       &g_x[(size_t)(m0 + row) * K_TOTAL + koff + ko]);
        }
        #pragma unroll
        for (int j = 0; j < 4; j++) {
            int c   = tid + j * 256;
            int row = c >> 2;
            int ko  = (c & 3) * 8;
            cp_async16(&Bs[buf * BSTAGE + row * AST + ko],
                       &g_w[(size_t)(n0 + row) * K_TOTAL + koff + ko]);
        }
    };

    #pragma unroll
    for (int s = 0; s < STAGES - 1; s++) {
        load_tiles(s, kbase + s * BK);
        asm volatile("cp.async.commit_group;\n");
    }
    asm volatile("cp.async.wait_group %0;\n" :: "n"(STAGES - 2));
    __syncthreads();

    unsigned int a0[4][4], b0[8][2], a1[4][4], b1[8][2];
    int rs = 0;
    int ws = STAGES - 1;
    frag_a_load(a0, &As[0], wm, lane, 0);
    frag_b_load8(b0, &Bs[0], wn, lane, 0);

    for (int kt = 0; kt < ktiles; kt++) {
        frag_a_load(a1, &As[rs * ASTAGE], wm, lane, 1);
        frag_b_load8(b1, &Bs[rs * BSTAGE], wn, lane, 1);
        if (kt + STAGES - 1 < ktiles) {
            load_tiles(ws, kbase + (kt + STAGES - 1) * BK);
        }
        ws = (ws + 1 == STAGES) ? 0 : ws + 1;
        asm volatile("cp.async.commit_group;\n");
        #pragma unroll
        for (int mt = 0; mt < 4; mt++)
            #pragma unroll
            for (int nt = 0; nt < 8; nt++) MMA16816(acc[mt][nt], a0[mt], b0[nt]);

        asm volatile("cp.async.wait_group %0;\n" :: "n"(STAGES - 2));
        __syncthreads();
        rs = (rs + 1 == STAGES) ? 0 : rs + 1;
        frag_a_load(a0, &As[rs * ASTAGE], wm, lane, 0);
        frag_b_load8(b0, &Bs[rs * BSTAGE], wn, lane, 0);
        #pragma unroll
        for (int mt = 0; mt < 4; mt++)
            #pragma unroll
            for (int nt = 0; nt < 8; nt++) MMA16816(acc[mt][nt], a1[mt], b1[nt]);
    }
}

// ---------------------------------------------------------------------------
// Combined GEMM: blocks [0, MAIN_TILES) -> out; rest -> K-split tail partials.
// ---------------------------------------------------------------------------
__global__ __launch_bounds__(256, 1)
void gemm_f16_kernel(const float* __restrict__ scale,
                     const float* __restrict__ bias,
                     float* __restrict__ out) {
    extern __shared__ __half smem[];
    __half* As = smem;
    __half* Bs = smem + STAGES * ASTAGE;

    const int tid  = threadIdx.x;
    const int lane = tid & 31;
    const int warp = tid >> 5;
    const int wm   = (warp >> 2) * 64;
    const int wn   = (warp & 3) * 64;

    float acc[4][8][4];
    #pragma unroll
    for (int i = 0; i < 4; i++)
        #pragma unroll
        for (int j = 0; j < 8; j++)
            #pragma unroll
            for (int r = 0; r < 4; r++) acc[i][j][r] = 0.0f;

    const int g = lane >> 2;
    const int t = lane & 3;

    if (blockIdx.x < MAIN_TILES) {
        int m0, n0;
        tile_coords(blockIdx.x, m0, n0);
        gemm_body(As, Bs, m0, n0, 0, KT, tid, lane, wm, wn, acc);

        #pragma unroll
        for (int nt = 0; nt < 8; nt++) {
            const int col = n0 + wn + nt * 8 + t * 2;
            const float s0 = __ldg(&scale[col]);
            const float s1 = __ldg(&scale[col + 1]);
            const float bb0 = __ldg(&bias[col]);
            const float bb1 = __ldg(&bias[col + 1]);
            #pragma unroll
            for (int mt = 0; mt < 4; mt++) {
                const int row0 = m0 + wm + mt * 16 + g;
                float2 v0, v1;
                v0.x = acc[mt][nt][0] * s0 + bb0;
                v0.y = acc[mt][nt][1] * s1 + bb1;
                v1.x = acc[mt][nt][2] * s0 + bb0;
                v1.y = acc[mt][nt][3] * s1 + bb1;
                *(float2*)&out[(size_t)row0 * N_TOTAL + col] = v0;
                *(float2*)&out[(size_t)(row0 + 8) * N_TOTAL + col] = v1;
            }
        }
    } else {
        const int pidx  = blockIdx.x - MAIN_TILES;   // 0..131
        const int tile  = pidx % TAIL_TILES;
        const int split = pidx / TAIL_TILES;
        const int kstart = (split == 0) ? 0 : (split == 1 ? 43 : 86);
        const int kcount = (split == 2) ? 42 : 43;

        int m0, n0;
        tile_coords(MAIN_TILES + tile, m0, n0);
        gemm_body(As, Bs, m0, n0, kstart * BK, kcount, tid, lane, wm, wn, acc);

        float* dst = &g_part[((size_t)split * TAIL_TILES + tile) * (BM * BN)];
        #pragma unroll
        for (int nt = 0; nt < 8; nt++) {
            const int col = wn + nt * 8 + t * 2;
            #pragma unroll
            for (int mt = 0; mt < 4; mt++) {
                const int row0 = wm + mt * 16 + g;
                *(float2*)&dst[row0 * BN + col] =
                    make_float2(acc[mt][nt][0], acc[mt][nt][1]);
                *(float2*)&dst[(row0 + 8) * BN + col] =
                    make_float2(acc[mt][nt][2], acc[mt][nt][3]);
            }
        }
    }
}

// ---------------------------------------------------------------------------
// Tail reduce: out = (p0 + p1 + p2) * scale + bias for the 44 tail tiles.
// ---------------------------------------------------------------------------
__global__ void tail_reduce_kernel(const float* __restrict__ scale,
                                   const float* __restrict__ bias,
                                   float* __restrict__ out) {
    const int i4 = blockIdx.x * blockDim.x + threadIdx.x;
    const int PER_TILE4 = BM * BN / 4;                      // 8192
    const int tile = i4 / PER_TILE4;
    const int rem  = i4 % PER_TILE4;
    const int row  = rem / (BN / 4);
    const int c4   = rem % (BN / 4);

    const size_t ss = (size_t)TAIL_TILES * BM * BN / 4;
    const size_t base = (size_t)tile * PER_TILE4 + rem;
    const float4* p = (const float4*)g_part;
    float4 v0 = p[base];
    float4 v1 = p[base + ss];
    float4 v2 = p[base + 2 * ss];

    int m0, n0;
    tile_coords(MAIN_TILES + tile, m0, n0);
    const int col = n0 + c4 * 4;
    const float4 sc = *(const float4*)&scale[col];
    const float4 bb = *(const float4*)&bias[col];

    float4 r;
    r.x = (v0.x + v1.x + v2.x) * sc.x + bb.x;
    r.y = (v0.y + v1.y + v2.y) * sc.y + bb.y;
    r.z = (v0.z + v1.z + v2.z) * sc.z + bb.z;
    r.w = (v0.w + v1.w + v2.w) * sc.w + bb.w;
    *(float4*)&out[(size_t)(m0 + row) * N_TOTAL + col] = r;
}

// ---------------------------------------------------------------------------
extern "C" void kernel_launch(void* const* d_in, const int* in_sizes, int n_in,
                              void* d_out, int out_size) {
    const float* x     = (const float*)d_in[0];
    const int*   wp    = (const int*)d_in[1];
    const float* scale = (const float*)d_in[2];
    const float* bias  = (const float*)d_in[3];
    float*       out   = (float*)d_out;

    convert_x_kernel<<<8192, 256>>>(x);
    // 22,544,384 int32 / 16 per thread = 1,409,024 threads -> 5504 blocks
    convert_w_kernel<<<5504, 256>>>(wp);

    const int smem_bytes = STAGES * (ASTAGE + BSTAGE) * sizeof(__half);  // 184320
    cudaFuncSetAttribute(gemm_f16_kernel,
                         cudaFuncAttributeMaxDynamicSharedMemorySize, smem_bytes);
    gemm_f16_kernel<<<MAIN_TILES + PART_CTAS, 256, smem_bytes>>>(scale, bias, out);

    tail_reduce_kernel<<<1408, 256>>>(scale, bias, out);
}

// round 12
// speedup vs baseline: 1.0366x; 1.0366x over previous
#include <cuda_runtime.h>
#include <cuda_fp16.h>

#define M_TOTAL 4096
#define N_TOTAL 11008
#define K_TOTAL 4096

// Scratch: fp16 copies of x and unpacked integer weights (exact in fp16).
__device__ __align__(16) __half g_x[(size_t)M_TOTAL * K_TOTAL];   // 33.5 MB
__device__ __align__(16) __half g_w[(size_t)N_TOTAL * K_TOTAL];   // 90.2 MB

#define BM 128
#define BN 256
#define BK 32
#define STAGES 5
#define KT (K_TOTAL / BK)          // 128
#define AST 40
#define ASTAGE (BM * AST)
#define BSTAGE (BN * AST)

#define TOTAL_TILES ((M_TOTAL / BM) * (N_TOTAL / BN))   // 1376
#define MAIN_TILES  1332                                 // 9 * 148
#define TAIL_TILES  (TOTAL_TILES - MAIN_TILES)           // 44
#define KSPLITS     3
#define PART_CTAS   (TAIL_TILES * KSPLITS)               // 132

// fp32 partials for the K-split tail: [split][tile][128][256]
__device__ __align__(16) float g_part[(size_t)KSPLITS * TAIL_TILES * BM * BN]; // 17.3MB

// Streaming stores (evict-first): out / g_part are not re-read on the hot path.
__device__ __forceinline__ void stcs_f2(float* p, float2 v) {
    asm volatile("st.global.cs.v2.f32 [%0], {%1, %2};" :: "l"(p), "f"(v.x), "f"(v.y) : "memory");
}
__device__ __forceinline__ void stcs_f4(float* p, float4 v) {
    asm volatile("st.global.cs.v4.f32 [%0], {%1, %2, %3, %4};"
                 :: "l"(p), "f"(v.x), "f"(v.y), "f"(v.z), "f"(v.w) : "memory");
}

// ---------------------------------------------------------------------------
// Fused pre-pass: blocks [0,8192) convert x; blocks [8192, 8192+11008) convert w.
// ---------------------------------------------------------------------------
__device__ __forceinline__ __half2 unpack_pair(int v) {
    int lo = (v & 15) - 8;
    int hi = ((v >> 4) & 15) - 8;
    return __halves2half2(__int2half_rn(lo), __int2half_rn(hi));
}

__global__ void convert_kernel(const float* __restrict__ x,
                               const int* __restrict__ wp) {
    if (blockIdx.x < 8192) {
        int i = blockIdx.x * blockDim.x + threadIdx.x;
        const float4* xv = (const float4*)x;
        float4 a = xv[2 * i];
        float4 b = xv[2 * i + 1];
        __half2 h0 = __floats2half2_rn(a.x, a.y);
        __half2 h1 = __floats2half2_rn(a.z, a.w);
        __half2 h2 = __floats2half2_rn(b.x, b.y);
        __half2 h3 = __floats2half2_rn(b.z, b.w);
        uint4 u;
        u.x = *(const unsigned int*)&h0;
        u.y = *(const unsigned int*)&h1;
        u.z = *(const unsigned int*)&h2;
        u.w = *(const unsigned int*)&h3;
        ((uint4*)g_x)[i] = u;
    } else {
        int i = (blockIdx.x - 8192) * blockDim.x + threadIdx.x;
        int4 p0 = ((const int4*)wp)[2 * i];
        int4 p1 = ((const int4*)wp)[2 * i + 1];
        uint4 u0, u1;
        {
            __half2 h0 = unpack_pair(p0.x), h1 = unpack_pair(p0.y);
            __half2 h2 = unpack_pair(p0.z), h3 = unpack_pair(p0.w);
            u0.x = *(const unsigned int*)&h0; u0.y = *(const unsigned int*)&h1;
            u0.z = *(const unsigned int*)&h2; u0.w = *(const unsigned int*)&h3;
        }
        {
            __half2 h0 = unpack_pair(p1.x), h1 = unpack_pair(p1.y);
            __half2 h2 = unpack_pair(p1.z), h3 = unpack_pair(p1.w);
            u1.x = *(const unsigned int*)&h0; u1.y = *(const unsigned int*)&h1;
            u1.z = *(const unsigned int*)&h2; u1.w = *(const unsigned int*)&h3;
        }
        ((uint4*)g_w)[2 * i]     = u0;
        ((uint4*)g_w)[2 * i + 1] = u1;
    }
}

// ---------------------------------------------------------------------------
// GEMM machinery (round-8 code, byte-identical mainloop)
// ---------------------------------------------------------------------------
__device__ __forceinline__ void cp_async16(void* smem_p, const void* gmem) {
    unsigned int s = (unsigned int)__cvta_generic_to_shared(smem_p);
    asm volatile("cp.async.cg.shared.global [%0], [%1], 16;\n" :: "r"(s), "l"(gmem));
}

__device__ __forceinline__ void tile_coords(int pid, int& m0, int& n0) {
    const int PN = N_TOTAL / BN;   // 43
    const int GM = 16;
    int group = pid / (GM * PN);
    int rem   = pid % (GM * PN);
    m0 = (group * GM + (rem % GM)) * BM;
    n0 = (rem / GM) * BN;
}

__device__ __forceinline__ void frag_a_load(unsigned int a[4][4],
                                            const __half* A, int wm,
                                            int lane, int ks) {
    #pragma unroll
    for (int mt = 0; mt < 4; mt++) {
        int r  = wm + mt * 16 + (lane & 15);
        int kk = ks * 16 + ((lane >> 4) << 3);
        unsigned int addr = (unsigned int)__cvta_generic_to_shared(&A[r * AST + kk]);
        asm volatile("ldmatrix.sync.aligned.m8n8.x4.shared.b16 {%0,%1,%2,%3}, [%4];"
                     : "=r"(a[mt][0]), "=r"(a[mt][1]), "=r"(a[mt][2]), "=r"(a[mt][3])
                     : "r"(addr));
    }
}

__device__ __forceinline__ void frag_b_load8(unsigned int b[8][2],
                                             const __half* B, int wn,
                                             int lane, int ks) {
    #pragma unroll
    for (int np = 0; np < 4; np++) {
        int r  = wn + np * 16 + (((lane >> 4) & 1) << 3) + (lane & 7);
        int kk = ks * 16 + (((lane >> 3) & 1) << 3);
        unsigned int addr = (unsigned int)__cvta_generic_to_shared(&B[r * AST + kk]);
        asm volatile("ldmatrix.sync.aligned.m8n8.x4.shared.b16 {%0,%1,%2,%3}, [%4];"
                     : "=r"(b[2 * np][0]), "=r"(b[2 * np][1]),
                       "=r"(b[2 * np + 1][0]), "=r"(b[2 * np + 1][1])
                     : "r"(addr));
    }
}

#define MMA16816(acc, a, b)                                                  \
    asm volatile(                                                            \
        "mma.sync.aligned.m16n8k16.row.col.f32.f16.f16.f32 "                 \
        "{%0,%1,%2,%3}, {%4,%5,%6,%7}, {%8,%9}, {%0,%1,%2,%3};"              \
        : "+f"((acc)[0]), "+f"((acc)[1]), "+f"((acc)[2]), "+f"((acc)[3])     \
        : "r"((a)[0]), "r"((a)[1]), "r"((a)[2]), "r"((a)[3]),                \
          "r"((b)[0]), "r"((b)[1]))

__device__ __forceinline__ void gemm_body(__half* As, __half* Bs,
                                          int m0, int n0, int kbase, int ktiles,
                                          int tid, int lane, int wm, int wn,
                                          float acc[4][8][4]) {
    auto load_tiles = [&](int buf, int koff) {
        #pragma unroll
        for (int j = 0; j < 2; j++) {
            int c   = tid + j * 256;
            int row = c >> 2;
            int ko  = (c & 3) * 8;
            cp_async16(&As[buf * ASTAGE + row * AST + ko],
                       &g_x[(size_t)(m0 + row) * K_TOTAL + koff + ko]);
        }
        #pragma unroll
        for (int j = 0; j < 4; j++) {
            int c   = tid + j * 256;
            int row = c >> 2;
            int ko  = (c & 3) * 8;
            cp_async16(&Bs[buf * BSTAGE + row * AST + ko],
                       &g_w[(size_t)(n0 + row) * K_TOTAL + koff + ko]);
        }
    };

    #pragma unroll
    for (int s = 0; s < STAGES - 1; s++) {
        load_tiles(s, kbase + s * BK);
        asm volatile("cp.async.commit_group;\n");
    }
    asm volatile("cp.async.wait_group %0;\n" :: "n"(STAGES - 2));
    __syncthreads();

    unsigned int a0[4][4], b0[8][2], a1[4][4], b1[8][2];
    int rs = 0;
    int ws = STAGES - 1;
    frag_a_load(a0, &As[0], wm, lane, 0);
    frag_b_load8(b0, &Bs[0], wn, lane, 0);

    for (int kt = 0; kt < ktiles; kt++) {
        frag_a_load(a1, &As[rs * ASTAGE], wm, lane, 1);
        frag_b_load8(b1, &Bs[rs * BSTAGE], wn, lane, 1);
        if (kt + STAGES - 1 < ktiles) {
            load_tiles(ws, kbase + (kt + STAGES - 1) * BK);
        }
        ws = (ws + 1 == STAGES) ? 0 : ws + 1;
        asm volatile("cp.async.commit_group;\n");
        #pragma unroll
        for (int mt = 0; mt < 4; mt++)
            #pragma unroll
            for (int nt = 0; nt < 8; nt++) MMA16816(acc[mt][nt], a0[mt], b0[nt]);

        asm volatile("cp.async.wait_group %0;\n" :: "n"(STAGES - 2));
        __syncthreads();
        rs = (rs + 1 == STAGES) ? 0 : rs + 1;
        frag_a_load(a0, &As[rs * ASTAGE], wm, lane, 0);
        frag_b_load8(b0, &Bs[rs * BSTAGE], wn, lane, 0);
        #pragma unroll
        for (int mt = 0; mt < 4; mt++)
            #pragma unroll
            for (int nt = 0; nt < 8; nt++) MMA16816(acc[mt][nt], a1[mt], b1[nt]);
    }
}

// ---------------------------------------------------------------------------
// Combined GEMM: blocks [0, MAIN_TILES) -> out; rest -> K-split tail partials.
// All output stores are streaming (.cs) to avoid evicting A/B from L2.
// ---------------------------------------------------------------------------
__global__ __launch_bounds__(256, 1)
void gemm_f16_kernel(const float* __restrict__ scale,
                     const float* __restrict__ bias,
                     float* __restrict__ out) {
    extern __shared__ __half smem[];
    __half* As = smem;
    __half* Bs = smem + STAGES * ASTAGE;

    const int tid  = threadIdx.x;
    const int lane = tid & 31;
    const int warp = tid >> 5;
    const int wm   = (warp >> 2) * 64;
    const int wn   = (warp & 3) * 64;

    float acc[4][8][4];
    #pragma unroll
    for (int i = 0; i < 4; i++)
        #pragma unroll
        for (int j = 0; j < 8; j++)
            #pragma unroll
            for (int r = 0; r < 4; r++) acc[i][j][r] = 0.0f;

    const int g = lane >> 2;
    const int t = lane & 3;

    if (blockIdx.x < MAIN_TILES) {
        int m0, n0;
        tile_coords(blockIdx.x, m0, n0);
        gemm_body(As, Bs, m0, n0, 0, KT, tid, lane, wm, wn, acc);

        #pragma unroll
        for (int nt = 0; nt < 8; nt++) {
            const int col = n0 + wn + nt * 8 + t * 2;
            const float s0 = __ldg(&scale[col]);
            const float s1 = __ldg(&scale[col + 1]);
            const float bb0 = __ldg(&bias[col]);
            const float bb1 = __ldg(&bias[col + 1]);
            #pragma unroll
            for (int mt = 0; mt < 4; mt++) {
                const int row0 = m0 + wm + mt * 16 + g;
                float2 v0, v1;
                v0.x = acc[mt][nt][0] * s0 + bb0;
                v0.y = acc[mt][nt][1] * s1 + bb1;
                v1.x = acc[mt][nt][2] * s0 + bb0;
                v1.y = acc[mt][nt][3] * s1 + bb1;
                stcs_f2(&out[(size_t)row0 * N_TOTAL + col], v0);
                stcs_f2(&out[(size_t)(row0 + 8) * N_TOTAL + col], v1);
            }
        }
    } else {
        const int pidx  = blockIdx.x - MAIN_TILES;   // 0..131
        const int tile  = pidx % TAIL_TILES;
        const int split = pidx / TAIL_TILES;
        const int kstart = (split == 0) ? 0 : (split == 1 ? 43 : 86);
        const int kcount = (split == 2) ? 42 : 43;

        int m0, n0;
        tile_coords(MAIN_TILES + tile, m0, n0);
        gemm_body(As, Bs, m0, n0, kstart * BK, kcount, tid, lane, wm, wn, acc);

        float* dst = &g_part[((size_t)split * TAIL_TILES + tile) * (BM * BN)];
        #pragma unroll
        for (int nt = 0; nt < 8; nt++) {
            const int col = wn + nt * 8 + t * 2;
            #pragma unroll
            for (int mt = 0; mt < 4; mt++) {
                const int row0 = wm + mt * 16 + g;
                stcs_f2(&dst[row0 * BN + col],
                        make_float2(acc[mt][nt][0], acc[mt][nt][1]));
                stcs_f2(&dst[(row0 + 8) * BN + col],
                        make_float2(acc[mt][nt][2], acc[mt][nt][3]));
            }
        }
    }
}

// ---------------------------------------------------------------------------
// Tail reduce: out = (p0 + p1 + p2) * scale + bias for the 44 tail tiles.
// ---------------------------------------------------------------------------
__global__ void tail_reduce_kernel(const float* __restrict__ scale,
                                   const float* __restrict__ bias,
                                   float* __restrict__ out) {
    const int i4 = blockIdx.x * blockDim.x + threadIdx.x;
    const int PER_TILE4 = BM * BN / 4;                      // 8192
    const int tile = i4 / PER_TILE4;
    const int rem  = i4 % PER_TILE4;
    const int row  = rem / (BN / 4);
    const int c4   = rem % (BN / 4);

    const size_t ss = (size_t)TAIL_TILES * BM * BN / 4;
    const size_t base = (size_t)tile * PER_TILE4 + rem;
    const float4* p = (const float4*)g_part;
    float4 v0 = p[base];
    float4 v1 = p[base + ss];
    float4 v2 = p[base + 2 * ss];

    int m0, n0;
    tile_coords(MAIN_TILES + tile, m0, n0);
    const int col = n0 + c4 * 4;
    const float4 sc = *(const float4*)&scale[col];
    const float4 bb = *(const float4*)&bias[col];

    float4 r;
    r.x = (v0.x + v1.x + v2.x) * sc.x + bb.x;
    r.y = (v0.y + v1.y + v2.y) * sc.y + bb.y;
    r.z = (v0.z + v1.z + v2.z) * sc.z + bb.z;
    r.w = (v0.w + v1.w + v2.w) * sc.w + bb.w;
    stcs_f4(&out[(size_t)(m0 + row) * N_TOTAL + col], r);
}

// ---------------------------------------------------------------------------
extern "C" void kernel_launch(void* const* d_in, const int* in_sizes, int n_in,
                              void* d_out, int out_size) {
    const float* x     = (const float*)d_in[0];
    const int*   wp    = (const int*)d_in[1];
    const float* scale = (const float*)d_in[2];
    const float* bias  = (const float*)d_in[3];
    float*       out   = (float*)d_out;

    convert_kernel<<<8192 + 11008, 256>>>(x, wp);

    const int smem_bytes = STAGES * (ASTAGE + BSTAGE) * sizeof(__half);  // 153600
    cudaFuncSetAttribute(gemm_f16_kernel,
                         cudaFuncAttributeMaxDynamicSharedMemorySize, smem_bytes);
    gemm_f16_kernel<<<MAIN_TILES + PART_CTAS, 256, smem_bytes>>>(scale, bias, out);

    tail_reduce_kernel<<<1408, 256>>>(scale, bias, out);
}

// round 13
// speedup vs baseline: 1.0376x; 1.0009x over previous
#include <cuda_runtime.h>
#include <cuda_fp16.h>

#define M_TOTAL 4096
#define N_TOTAL 11008
#define K_TOTAL 4096

// Scratch: fp16 copies of x and unpacked integer weights (exact in fp16).
__device__ __align__(16) __half g_x[(size_t)M_TOTAL * K_TOTAL];   // 33.5 MB
__device__ __align__(16) __half g_w[(size_t)N_TOTAL * K_TOTAL];   // 90.2 MB

#define BM 128
#define BN 256
#define BK 32
#define STAGES 5
#define KT (K_TOTAL / BK)          // 128
#define AST 40
#define ASTAGE (BM * AST)
#define BSTAGE (BN * AST)

#define TOTAL_TILES ((M_TOTAL / BM) * (N_TOTAL / BN))   // 1376
#define MAIN_TILES  1332                                 // 9 * 148
#define TAIL_TILES  (TOTAL_TILES - MAIN_TILES)           // 44
#define KSPLITS     3
#define PART_CTAS   (TAIL_TILES * KSPLITS)               // 132

// fp32 partials for the K-split tail: [split][tile][128][256]
__device__ __align__(16) float g_part[(size_t)KSPLITS * TAIL_TILES * BM * BN]; // 17.3MB

// Streaming stores (evict-first): out / g_part are not re-read on the hot path.
__device__ __forceinline__ void stcs_f2(float* p, float2 v) {
    asm volatile("st.global.cs.v2.f32 [%0], {%1, %2};" :: "l"(p), "f"(v.x), "f"(v.y) : "memory");
}
__device__ __forceinline__ void stcs_f4(float* p, float4 v) {
    asm volatile("st.global.cs.v4.f32 [%0], {%1, %2, %3, %4};"
                 :: "l"(p), "f"(v.x), "f"(v.y), "f"(v.z), "f"(v.w) : "memory");
}
// Streaming 16B loads (evict-first): inputs read exactly once.
__device__ __forceinline__ uint4 ldcs_u4(const void* p) {
    uint4 v;
    asm volatile("ld.global.cs.v4.u32 {%0, %1, %2, %3}, [%4];"
                 : "=r"(v.x), "=r"(v.y), "=r"(v.z), "=r"(v.w) : "l"(p));
    return v;
}
__device__ __forceinline__ float4 ldcs_f4(const void* p) {
    float4 v;
    asm volatile("ld.global.cs.v4.f32 {%0, %1, %2, %3}, [%4];"
                 : "=f"(v.x), "=f"(v.y), "=f"(v.z), "=f"(v.w) : "l"(p));
    return v;
}

// ---------------------------------------------------------------------------
// Fused pre-pass: blocks [0,8192) convert x; blocks [8192, 8192+11008) convert w.
// Inputs are read-once -> streaming loads.
// ---------------------------------------------------------------------------
__device__ __forceinline__ __half2 unpack_pair(int v) {
    int lo = (v & 15) - 8;
    int hi = ((v >> 4) & 15) - 8;
    return __halves2half2(__int2half_rn(lo), __int2half_rn(hi));
}

__global__ void convert_kernel(const float* __restrict__ x,
                               const int* __restrict__ wp) {
    if (blockIdx.x < 8192) {
        int i = blockIdx.x * blockDim.x + threadIdx.x;
        const float4* xv = (const float4*)x;
        float4 a = ldcs_f4(&xv[2 * i]);
        float4 b = ldcs_f4(&xv[2 * i + 1]);
        __half2 h0 = __floats2half2_rn(a.x, a.y);
        __half2 h1 = __floats2half2_rn(a.z, a.w);
        __half2 h2 = __floats2half2_rn(b.x, b.y);
        __half2 h3 = __floats2half2_rn(b.z, b.w);
        uint4 u;
        u.x = *(const unsigned int*)&h0;
        u.y = *(const unsigned int*)&h1;
        u.z = *(const unsigned int*)&h2;
        u.w = *(const unsigned int*)&h3;
        ((uint4*)g_x)[i] = u;
    } else {
        int i = (blockIdx.x - 8192) * blockDim.x + threadIdx.x;
        uint4 q0 = ldcs_u4(&((const int4*)wp)[2 * i]);
        uint4 q1 = ldcs_u4(&((const int4*)wp)[2 * i + 1]);
        uint4 u0, u1;
        {
            __half2 h0 = unpack_pair((int)q0.x), h1 = unpack_pair((int)q0.y);
            __half2 h2 = unpack_pair((int)q0.z), h3 = unpack_pair((int)q0.w);
            u0.x = *(const unsigned int*)&h0; u0.y = *(const unsigned int*)&h1;
            u0.z = *(const unsigned int*)&h2; u0.w = *(const unsigned int*)&h3;
        }
        {
            __half2 h0 = unpack_pair((int)q1.x), h1 = unpack_pair((int)q1.y);
            __half2 h2 = unpack_pair((int)q1.z), h3 = unpack_pair((int)q1.w);
            u1.x = *(const unsigned int*)&h0; u1.y = *(const unsigned int*)&h1;
            u1.z = *(const unsigned int*)&h2; u1.w = *(const unsigned int*)&h3;
        }
        ((uint4*)g_w)[2 * i]     = u0;
        ((uint4*)g_w)[2 * i + 1] = u1;
    }
}

// ---------------------------------------------------------------------------
// GEMM machinery (round-8/12 code, byte-identical mainloop)
// ---------------------------------------------------------------------------
__device__ __forceinline__ void cp_async16(void* smem_p, const void* gmem) {
    unsigned int s = (unsigned int)__cvta_generic_to_shared(smem_p);
    asm volatile("cp.async.cg.shared.global [%0], [%1], 16;\n" :: "r"(s), "l"(gmem));
}

__device__ __forceinline__ void tile_coords(int pid, int& m0, int& n0) {
    const int PN = N_TOTAL / BN;   // 43
    const int GM = 16;
    int group = pid / (GM * PN);
    int rem   = pid % (GM * PN);
    m0 = (group * GM + (rem % GM)) * BM;
    n0 = (rem / GM) * BN;
}

__device__ __forceinline__ void frag_a_load(unsigned int a[4][4],
                                            const __half* A, int wm,
                                            int lane, int ks) {
    #pragma unroll
    for (int mt = 0; mt < 4; mt++) {
        int r  = wm + mt * 16 + (lane & 15);
        int kk = ks * 16 + ((lane >> 4) << 3);
        unsigned int addr = (unsigned int)__cvta_generic_to_shared(&A[r * AST + kk]);
        asm volatile("ldmatrix.sync.aligned.m8n8.x4.shared.b16 {%0,%1,%2,%3}, [%4];"
                     : "=r"(a[mt][0]), "=r"(a[mt][1]), "=r"(a[mt][2]), "=r"(a[mt][3])
                     : "r"(addr));
    }
}

__device__ __forceinline__ void frag_b_load8(unsigned int b[8][2],
                                             const __half* B, int wn,
                                             int lane, int ks) {
    #pragma unroll
    for (int np = 0; np < 4; np++) {
        int r  = wn + np * 16 + (((lane >> 4) & 1) << 3) + (lane & 7);
        int kk = ks * 16 + (((lane >> 3) & 1) << 3);
        unsigned int addr = (unsigned int)__cvta_generic_to_shared(&B[r * AST + kk]);
        asm volatile("ldmatrix.sync.aligned.m8n8.x4.shared.b16 {%0,%1,%2,%3}, [%4];"
                     : "=r"(b[2 * np][0]), "=r"(b[2 * np][1]),
                       "=r"(b[2 * np + 1][0]), "=r"(b[2 * np + 1][1])
                     : "r"(addr));
    }
}

#define MMA16816(acc, a, b)                                                  \
    asm volatile(                                                            \
        "mma.sync.aligned.m16n8k16.row.col.f32.f16.f16.f32 "                 \
        "{%0,%1,%2,%3}, {%4,%5,%6,%7}, {%8,%9}, {%0,%1,%2,%3};"              \
        : "+f"((acc)[0]), "+f"((acc)[1]), "+f"((acc)[2]), "+f"((acc)[3])     \
        : "r"((a)[0]), "r"((a)[1]), "r"((a)[2]), "r"((a)[3]),                \
          "r"((b)[0]), "r"((b)[1]))

__device__ __forceinline__ void gemm_body(__half* As, __half* Bs,
                                          int m0, int n0, int kbase, int ktiles,
                                          int tid, int lane, int wm, int wn,
                                          float acc[4][8][4]) {
    auto load_tiles = [&](int buf, int koff) {
        #pragma unroll
        for (int j = 0; j < 2; j++) {
            int c   = tid + j * 256;
            int row = c >> 2;
            int ko  = (c & 3) * 8;
            cp_async16(&As[buf * ASTAGE + row * AST + ko],
                       &g_x[(size_t)(m0 + row) * K_TOTAL + koff + ko]);
        }
        #pragma unroll
        for (int j = 0; j < 4; j++) {
            int c   = tid + j * 256;
            int row = c >> 2;
            int ko  = (c & 3) * 8;
            cp_async16(&Bs[buf * BSTAGE + row * AST + ko],
                       &g_w[(size_t)(n0 + row) * K_TOTAL + koff + ko]);
        }
    };

    #pragma unroll
    for (int s = 0; s < STAGES - 1; s++) {
        load_tiles(s, kbase + s * BK);
        asm volatile("cp.async.commit_group;\n");
    }
    asm volatile("cp.async.wait_group %0;\n" :: "n"(STAGES - 2));
    __syncthreads();

    unsigned int a0[4][4], b0[8][2], a1[4][4], b1[8][2];
    int rs = 0;
    int ws = STAGES - 1;
    frag_a_load(a0, &As[0], wm, lane, 0);
    frag_b_load8(b0, &Bs[0], wn, lane, 0);

    for (int kt = 0; kt < ktiles; kt++) {
        frag_a_load(a1, &As[rs * ASTAGE], wm, lane, 1);
        frag_b_load8(b1, &Bs[rs * BSTAGE], wn, lane, 1);
        if (kt + STAGES - 1 < ktiles) {
            load_tiles(ws, kbase + (kt + STAGES - 1) * BK);
        }
        ws = (ws + 1 == STAGES) ? 0 : ws + 1;
        asm volatile("cp.async.commit_group;\n");
        #pragma unroll
        for (int mt = 0; mt < 4; mt++)
            #pragma unroll
            for (int nt = 0; nt < 8; nt++) MMA16816(acc[mt][nt], a0[mt], b0[nt]);

        asm volatile("cp.async.wait_group %0;\n" :: "n"(STAGES - 2));
        __syncthreads();
        rs = (rs + 1 == STAGES) ? 0 : rs + 1;
        frag_a_load(a0, &As[rs * ASTAGE], wm, lane, 0);
        frag_b_load8(b0, &Bs[rs * BSTAGE], wn, lane, 0);
        #pragma unroll
        for (int mt = 0; mt < 4; mt++)
            #pragma unroll
            for (int nt = 0; nt < 8; nt++) MMA16816(acc[mt][nt], a1[mt], b1[nt]);
    }
}

// ---------------------------------------------------------------------------
// Combined GEMM: blocks [0, MAIN_TILES) -> out; rest -> K-split tail partials.
// All output stores are streaming (.cs) to avoid evicting A/B from L2.
// ---------------------------------------------------------------------------
__global__ __launch_bounds__(256, 1)
void gemm_f16_kernel(const float* __restrict__ scale,
                     const float* __restrict__ bias,
                     float* __restrict__ out) {
    extern __shared__ __half smem[];
    __half* As = smem;
    __half* Bs = smem + STAGES * ASTAGE;

    const int tid  = threadIdx.x;
    const int lane = tid & 31;
    const int warp = tid >> 5;
    const int wm   = (warp >> 2) * 64;
    const int wn   = (warp & 3) * 64;

    float acc[4][8][4];
    #pragma unroll
    for (int i = 0; i < 4; i++)
        #pragma unroll
        for (int j = 0; j < 8; j++)
            #pragma unroll
            for (int r = 0; r < 4; r++) acc[i][j][r] = 0.0f;

    const int g = lane >> 2;
    const int t = lane & 3;

    if (blockIdx.x < MAIN_TILES) {
        int m0, n0;
        tile_coords(blockIdx.x, m0, n0);
        gemm_body(As, Bs, m0, n0, 0, KT, tid, lane, wm, wn, acc);

        #pragma unroll
        for (int nt = 0; nt < 8; nt++) {
            const int col = n0 + wn + nt * 8 + t * 2;
            const float s0 = __ldg(&scale[col]);
            const float s1 = __ldg(&scale[col + 1]);
            const float bb0 = __ldg(&bias[col]);
            const float bb1 = __ldg(&bias[col + 1]);
            #pragma unroll
            for (int mt = 0; mt < 4; mt++) {
                const int row0 = m0 + wm + mt * 16 + g;
                float2 v0, v1;
                v0.x = acc[mt][nt][0] * s0 + bb0;
                v0.y = acc[mt][nt][1] * s1 + bb1;
                v1.x = acc[mt][nt][2] * s0 + bb0;
                v1.y = acc[mt][nt][3] * s1 + bb1;
                stcs_f2(&out[(size_t)row0 * N_TOTAL + col], v0);
                stcs_f2(&out[(size_t)(row0 + 8) * N_TOTAL + col], v1);
            }
        }
    } else {
        const int pidx  = blockIdx.x - MAIN_TILES;   // 0..131
        const int tile  = pidx % TAIL_TILES;
        const int split = pidx / TAIL_TILES;
        const int kstart = (split == 0) ? 0 : (split == 1 ? 43 : 86);
        const int kcount = (split == 2) ? 42 : 43;

        int m0, n0;
        tile_coords(MAIN_TILES + tile, m0, n0);
        gemm_body(As, Bs, m0, n0, kstart * BK, kcount, tid, lane, wm, wn, acc);

        float* dst = &g_part[((size_t)split * TAIL_TILES + tile) * (BM * BN)];
        #pragma unroll
        for (int nt = 0; nt < 8; nt++) {
            const int col = wn + nt * 8 + t * 2;
            #pragma unroll
            for (int mt = 0; mt < 4; mt++) {
                const int row0 = wm + mt * 16 + g;
                stcs_f2(&dst[row0 * BN + col],
                        make_float2(acc[mt][nt][0], acc[mt][nt][1]));
                stcs_f2(&dst[(row0 + 8) * BN + col],
                        make_float2(acc[mt][nt][2], acc[mt][nt][3]));
            }
        }
    }
}

// ---------------------------------------------------------------------------
// Tail reduce: out = (p0 + p1 + p2) * scale + bias for the 44 tail tiles.
// g_part is read-once -> streaming loads.
// ---------------------------------------------------------------------------
__global__ void tail_reduce_kernel(const float* __restrict__ scale,
                                   const float* __restrict__ bias,
                                   float* __restrict__ out) {
    const int i4 = blockIdx.x * blockDim.x + threadIdx.x;
    const int PER_TILE4 = BM * BN / 4;                      // 8192
    const int tile = i4 / PER_TILE4;
    const int rem  = i4 % PER_TILE4;
    const int row  = rem / (BN / 4);
    const int c4   = rem % (BN / 4);

    const size_t ss = (size_t)TAIL_TILES * BM * BN / 4;
    const size_t base = (size_t)tile * PER_TILE4 + rem;
    const float4* p = (const float4*)g_part;
    float4 v0 = ldcs_f4(&p[base]);
    float4 v1 = ldcs_f4(&p[base + ss]);
    float4 v2 = ldcs_f4(&p[base + 2 * ss]);

    int m0, n0;
    tile_coords(MAIN_TILES + tile, m0, n0);
    const int col = n0 + c4 * 4;
    const float4 sc = *(const float4*)&scale[col];
    const float4 bb = *(const float4*)&bias[col];

    float4 r;
    r.x = (v0.x + v1.x + v2.x) * sc.x + bb.x;
    r.y = (v0.y + v1.y + v2.y) * sc.y + bb.y;
    r.z = (v0.z + v1.z + v2.z) * sc.z + bb.z;
    r.w = (v0.w + v1.w + v2.w) * sc.w + bb.w;
    stcs_f4(&out[(size_t)(m0 + row) * N_TOTAL + col], r);
}

// ---------------------------------------------------------------------------
extern "C" void kernel_launch(void* const* d_in, const int* in_sizes, int n_in,
                              void* d_out, int out_size) {
    const float* x     = (const float*)d_in[0];
    const int*   wp    = (const int*)d_in[1];
    const float* scale = (const float*)d_in[2];
    const float* bias  = (const float*)d_in[3];
    float*       out   = (float*)d_out;

    convert_kernel<<<8192 + 11008, 256>>>(x, wp);

    const int smem_bytes = STAGES * (ASTAGE + BSTAGE) * sizeof(__half);  // 153600
    cudaFuncSetAttribute(gemm_f16_kernel,
                         cudaFuncAttributeMaxDynamicSharedMemorySize, smem_bytes);
    gemm_f16_kernel<<<MAIN_TILES + PART_CTAS, 256, smem_bytes>>>(scale, bias, out);

    tail_reduce_kernel<<<1408, 256>>>(scale, bias, out);
}